// round 15
// baseline (speedup 1.0000x reference)
#include <cuda_runtime.h>
#include <cuda_bf16.h>
#include <cstdint>

// Problem constants
#define BB 8
#define SS 8192
#define DD 768
#define VV 64
#define LL 26
#define NSEG  (BB * VV)     // 512
#define NCH   18            // chunks per batch
#define CHTOK 448           // tokens per regular chunk; last chunk = 576
#define NCTA  (BB * NCH)    // 144 CTAs
#define NTHR1 512
#define NN    32            // padded label columns
#define WPAD  776           // W smem k-stride (768 + 8 pad, bank shift)
#define APAD  264           // A smem k-stride (256 + 8 pad)

// Scratch: per-chunk binned logit sums + counts. Overwritten every run.
__device__ float g_bins[NCTA * VV * NN];   // 1.18 MB
__device__ int   g_cnts[NCTA * VV];

static __device__ __forceinline__ uint32_t pk(__nv_bfloat16 lo, __nv_bfloat16 hi) {
    return ((uint32_t)__bfloat16_as_ushort(hi) << 16) | __bfloat16_as_ushort(lo);
}
// Split (x,y) into packed bf16 hi-pair and lo-pair (x in low half).
static __device__ __forceinline__ void split2(float x, float y,
                                              uint32_t& hi, uint32_t& lo) {
    __nv_bfloat16 hx = __float2bfloat16(x);
    __nv_bfloat16 hy = __float2bfloat16(y);
    float rx = x - __bfloat162float(hx);
    float ry = y - __bfloat162float(hy);
    hi = pk(hx, hy);
    lo = pk(__float2bfloat16(rx), __float2bfloat16(ry));
}

static __device__ __forceinline__ void mma16816(float d[4],
        uint32_t a0, uint32_t a1, uint32_t a2, uint32_t a3,
        uint32_t b0, uint32_t b1) {
    asm volatile(
        "mma.sync.aligned.m16n8k16.row.col.f32.bf16.bf16.f32 "
        "{%0,%1,%2,%3}, {%4,%5,%6,%7}, {%8,%9}, {%0,%1,%2,%3};"
        : "+f"(d[0]), "+f"(d[1]), "+f"(d[2]), "+f"(d[3])
        : "r"(a0), "r"(a1), "r"(a2), "r"(a3), "r"(b0), "r"(b1));
}

// ---------------------------------------------------------------------------
// Kernel 1: sequential-streaming projection + per-symbol logit binning.
// One CTA per (batch, token-chunk). Tokens read in order (DRAM-friendly).
__global__ __launch_bounds__(NTHR1, 1) void k_stream(
    const float* __restrict__ h,      // [B*S, D]
    const int*   __restrict__ ids,    // [B*S]
    const float* __restrict__ Wm)     // [L, D]
{
    extern __shared__ char smem[];
    __nv_bfloat16* sWh = (__nv_bfloat16*)smem;            // [32][WPAD]
    __nv_bfloat16* sWl = sWh + 32 * WPAD;
    __nv_bfloat16* sAh = sWl + 32 * WPAD;                 // [64][APAD]
    __nv_bfloat16* sAl = sAh + 64 * APAD;
    float* sbins = (float*)(sAl + 64 * APAD);             // [64][32]
    int*   sids  = (int*)(sbins + VV * NN);               // [576]
    int*   scnt  = sids + 576;                            // [64]

    const int cta  = blockIdx.x;
    const int b    = cta / NCH;
    const int j    = cta % NCH;
    const int ch0  = j * CHTOK;
    const int ntok = (j == NCH - 1) ? (SS - (NCH - 1) * CHTOK) : CHTOK;
    const int ntil = ntok >> 6;       // 7 or 9 tiles of 64 tokens

    const int tid  = threadIdx.x;
    const int warp = tid >> 5;        // 0..15
    const int lane = tid & 31;
    const int mrow0 = (warp & 3) * 16;
    const int ncol0 = (warp >> 2) * 8;

    // ---- Prep: zero W smem + bins + counts, load ids ----
    for (int i = tid; i < 32 * WPAD; i += NTHR1) { sWh[i] = __float2bfloat16(0.f); sWl[i] = __float2bfloat16(0.f); }
    for (int i = tid; i < VV * NN; i += NTHR1) sbins[i] = 0.f;
    for (int i = tid; i < VV; i += NTHR1) scnt[i] = 0;
    for (int i = tid; i < ntok; i += NTHR1) sids[i] = ids[b * SS + ch0 + i];
    __syncthreads();

    // Fill W hi/lo (rows 0..25, k 0..767)
    {
        const float4* __restrict__ Wp4 = (const float4*)Wm;
        for (int idx = tid; idx < LL * (DD / 4); idx += NTHR1) {
            const int row = idx / (DD / 4);
            const int kf4 = idx % (DD / 4);
            float4 w = __ldg(&Wp4[idx]);
            const int k0 = kf4 * 4;
            uint32_t h0, l0, h1, l1;
            split2(w.x, w.y, h0, l0);
            split2(w.z, w.w, h1, l1);
            *(uint32_t*)&sWh[row * WPAD + k0]     = h0;
            *(uint32_t*)&sWh[row * WPAD + k0 + 2] = h1;
            *(uint32_t*)&sWl[row * WPAD + k0]     = l0;
            *(uint32_t*)&sWl[row * WPAD + k0 + 2] = l1;
        }
    }
    // Count histogram
    for (int i = tid; i < ntok; i += NTHR1) atomicAdd(&scnt[sids[i]], 1);
    __syncthreads();

    // Staging thread mapping: token = tid/8, slot = tid%8, 8 float4 each.
    const int stok  = tid >> 3;
    const int slot  = tid & 7;
    const float4* __restrict__ hp4 =
        (const float4*)h + (size_t)(b * SS + ch0) * (DD / 4);

    // Prefetch stage (mt=0, sl=0)
    float4 R[8];
    #pragma unroll
    for (int q = 0; q < 8; ++q)
        R[q] = __ldg(&hp4[(size_t)stok * (DD / 4) + slot + 8 * q]);

    const int nstage = ntil * 3;

    for (int mt = 0; mt < ntil; ++mt) {
        float acc[4] = {0.f, 0.f, 0.f, 0.f};

        for (int sl = 0; sl < 3; ++sl) {
            // Store prefetched slice (split to bf16 hi/lo)
            #pragma unroll
            for (int q = 0; q < 8; ++q) {
                const int k0 = (slot + 8 * q) * 4;
                uint32_t h0, l0, h1, l1;
                split2(R[q].x, R[q].y, h0, l0);
                split2(R[q].z, R[q].w, h1, l1);
                *(uint32_t*)&sAh[stok * APAD + k0]     = h0;
                *(uint32_t*)&sAh[stok * APAD + k0 + 2] = h1;
                *(uint32_t*)&sAl[stok * APAD + k0]     = l0;
                *(uint32_t*)&sAl[stok * APAD + k0 + 2] = l1;
            }
            __syncthreads();

            // Prefetch next stage while computing
            const int stage = mt * 3 + sl + 1;
            if (stage < nstage) {
                const int nmt = stage / 3, nsl = stage % 3;
                const size_t base =
                    (size_t)(nmt * 64 + stok) * (DD / 4) + nsl * 64 + slot;
                #pragma unroll
                for (int q = 0; q < 8; ++q) R[q] = __ldg(&hp4[base + 8 * q]);
            }

            // Compute: 16 k-steps of 3 MMAs
            const __nv_bfloat16* aBh = sAh + (mrow0 + (lane >> 2)) * APAD + 2 * (lane & 3);
            const __nv_bfloat16* aBl = sAl + (mrow0 + (lane >> 2)) * APAD + 2 * (lane & 3);
            const __nv_bfloat16* bBh = sWh + (ncol0 + (lane >> 2)) * WPAD + sl * 256 + 2 * (lane & 3);
            const __nv_bfloat16* bBl = sWl + (ncol0 + (lane >> 2)) * WPAD + sl * 256 + 2 * (lane & 3);
            #pragma unroll
            for (int ks = 0; ks < 16; ++ks) {
                const int ko = ks * 16;
                uint32_t ah0 = *(const uint32_t*)&aBh[ko];
                uint32_t ah1 = *(const uint32_t*)&aBh[ko + 8 * APAD];
                uint32_t ah2 = *(const uint32_t*)&aBh[ko + 8];
                uint32_t ah3 = *(const uint32_t*)&aBh[ko + 8 * APAD + 8];
                uint32_t bh0 = *(const uint32_t*)&bBh[ko];
                uint32_t bh1 = *(const uint32_t*)&bBh[ko + 8];
                mma16816(acc, ah0, ah1, ah2, ah3, bh0, bh1);
                uint32_t al0 = *(const uint32_t*)&aBl[ko];
                uint32_t al1 = *(const uint32_t*)&aBl[ko + 8 * APAD];
                uint32_t al2 = *(const uint32_t*)&aBl[ko + 8];
                uint32_t al3 = *(const uint32_t*)&aBl[ko + 8 * APAD + 8];
                mma16816(acc, al0, al1, al2, al3, bh0, bh1);
                uint32_t bl0 = *(const uint32_t*)&bBl[ko];
                uint32_t bl1 = *(const uint32_t*)&bBl[ko + 8];
                mma16816(acc, ah0, ah1, ah2, ah3, bl0, bl1);
            }
            __syncthreads();
        }

        // Epilogue: scatter this tile's logits into per-symbol bins.
        {
            const int r0  = mrow0 + (lane >> 2);
            const int col = ncol0 + 2 * (lane & 3);
            const int id0 = sids[mt * 64 + r0];
            const int id1 = sids[mt * 64 + r0 + 8];
            atomicAdd(&sbins[id0 * NN + col],     acc[0]);
            atomicAdd(&sbins[id0 * NN + col + 1], acc[1]);
            atomicAdd(&sbins[id1 * NN + col],     acc[2]);
            atomicAdd(&sbins[id1 * NN + col + 1], acc[3]);
        }
    }
    __syncthreads();

    // Flush bins + counts to scratch (plain stores).
    for (int i = tid; i < VV * NN; i += NTHR1)
        g_bins[cta * (VV * NN) + i] = sbins[i];
    for (int i = tid; i < VV; i += NTHR1)
        g_cnts[cta * VV + i] = scnt[i];
}

// ---------------------------------------------------------------------------
// Kernel 2: one warp per segment — reduce 18 chunks, mean + bias, mask.
__global__ __launch_bounds__(256) void k_head(
    const float* __restrict__ bias, float* __restrict__ out)
{
    const int w    = (blockIdx.x * 256 + threadIdx.x) >> 5;
    const int lane = threadIdx.x & 31;
    if (w >= NSEG) return;
    const int b = w >> 6, v = w & 63;

    int c = (lane < NCH) ? g_cnts[(b * NCH + lane) * VV + v] : 0;
    #pragma unroll
    for (int o = 16; o; o >>= 1) c += __shfl_xor_sync(0xffffffffu, c, o);
    c = __shfl_sync(0xffffffffu, c, 0);

    if (lane < LL) {
        float s = 0.f;
        #pragma unroll
        for (int j2 = 0; j2 < NCH; ++j2)
            s += g_bins[((b * NCH + j2) * VV + v) * NN + lane];
        float r = (v != 0 && c > 0) ? (s / (float)c + __ldg(&bias[lane])) : 0.0f;
        out[w * LL + lane] = r;
    }
}

// ---------------------------------------------------------------------------
#define SMEMB ((2 * 32 * WPAD + 2 * 64 * APAD) * 2 + VV * NN * 4 + 576 * 4 + VV * 4)

extern "C" void kernel_launch(void* const* d_in, const int* in_sizes, int n_in,
                              void* d_out, int out_size) {
    const float* h    = nullptr;   // 50331648
    const float* Wm   = nullptr;   // 19968
    const float* bias = nullptr;   // 26
    const int*   ids  = nullptr;   // 65536
    for (int i = 0; i < n_in; ++i) {
        switch (in_sizes[i]) {
            case BB * SS * DD: h    = (const float*)d_in[i]; break;
            case LL * DD:      Wm   = (const float*)d_in[i]; break;
            case LL:           bias = (const float*)d_in[i]; break;
            case BB * SS:      ids  = (const int*)d_in[i];   break;
        }
    }
    float* out = (float*)d_out;

    cudaFuncSetAttribute(k_stream,
                         cudaFuncAttributeMaxDynamicSharedMemorySize, SMEMB);
    k_stream<<<NCTA, NTHR1, SMEMB>>>(h, ids, Wm);
    k_head<<<(NSEG * 32 + 255) / 256, 256>>>(bias, out);
}

// round 16
// speedup vs baseline: 1.4285x; 1.4285x over previous
#include <cuda_runtime.h>
#include <cstdint>
#include <cstddef>

// Problem constants
#define BB 8
#define SS 8192
#define DD 768
#define VV 64
#define LL 26
#define NSEG  (BB * VV)     // 512
#define NCH   18            // chunks per batch: 16 x 448 tok + 2 x 512 tok
#define NCTA  (BB * NCH)    // 144 CTAs (single wave)
#define NTHR1 512
#define NN    32            // padded label columns
#define KS    192           // k-slice width (4 slices cover D=768)
#define APADF 204           // A smem row stride in floats (192+12, conflict-free)
#define WPADF 772           // W smem row stride in floats (768+4, conflict-free)

// tf32 truncation bias compensation (E[rel loss] = 2^-11 * E[1/m] ~ 3.52e-4)
#define COMP 1.000352f

// Scratch: per-chunk binned logit sums + counts (fully overwritten each run).
__device__ float g_bins[NCTA * VV * NN];   // 1.18 MB
__device__ int   g_cnts[NCTA * VV];

// Shared memory byte offsets (dynamic smem, all 16B aligned)
#define OFF_W    0
#define SZ_W     (32 * WPADF * 4)            // 98816
#define OFF_A    (OFF_W + SZ_W)
#define SZ_ABUF  (64 * APADF * 4)            // 52224
#define OFF_BINS (OFF_A + 2 * SZ_ABUF)       // 203264
#define OFF_IDS  (OFF_BINS + VV * NN * 4)    // 211456
#define OFF_CNT  (OFF_IDS + 576 * 4)         // 213760
#define SMEMB    (OFF_CNT + VV * 4)          // 214016

static __device__ __forceinline__ uint32_t smem_u32(const void* p) {
    return (uint32_t)__cvta_generic_to_shared(p);
}
static __device__ __forceinline__ uint32_t f32_to_tf32_rna(float w) {
    uint32_t u = __float_as_uint(w);
    return (u + 0x1000u) & 0xFFFFE000u;
}
static __device__ __forceinline__ void mma_tf32(float d[4],
        uint32_t a0, uint32_t a1, uint32_t a2, uint32_t a3,
        uint32_t b0, uint32_t b1) {
    asm volatile(
        "mma.sync.aligned.m16n8k8.row.col.f32.tf32.tf32.f32 "
        "{%0,%1,%2,%3}, {%4,%5,%6,%7}, {%8,%9}, {%0,%1,%2,%3};"
        : "+f"(d[0]), "+f"(d[1]), "+f"(d[2]), "+f"(d[3])
        : "r"(a0), "r"(a1), "r"(a2), "r"(a3), "r"(b0), "r"(b1));
}

// ---------------------------------------------------------------------------
// Kernel 1: sequential streaming h -> tf32 MMA vs W -> per-symbol logit bins.
__global__ __launch_bounds__(NTHR1, 1) void k_stream(
    const float* __restrict__ h,      // [B*S, D]
    const int*   __restrict__ ids,    // [B*S]
    const float* __restrict__ Wm)     // [L, D]
{
    extern __shared__ char smem[];
    float* sW    = (float*)(smem + OFF_W);
    float* sbins = (float*)(smem + OFF_BINS);
    int*   sids  = (int*)(smem + OFF_IDS);
    int*   scnt  = (int*)(smem + OFF_CNT);

    const int cta  = blockIdx.x;
    const int b    = cta / NCH;
    const int j    = cta % NCH;
    const int s0   = (j < 16) ? j * 448 : 7168 + (j - 16) * 512;
    const int ntil = (j < 16) ? 7 : 8;          // 64-token tiles
    const int ntok = ntil * 64;
    const int nst  = ntil * 4;                  // stages (4 k-slices per tile)

    const int tid  = threadIdx.x;
    const int warp = tid >> 5;
    const int lane = tid & 31;
    const int g    = lane >> 2;                 // group id
    const int tig  = lane & 3;                  // thread in group
    const int mrow0 = (warp & 3) * 16;
    const int ncol0 = (warp >> 2) * 8;

    // ---- Prologue: W (tf32-rounded, zero-padded), bins, counts, ids ----
    for (int i = tid; i < 32 * WPADF; i += NTHR1) {
        const int row = i / WPADF, col = i % WPADF;
        uint32_t t = 0;
        if (row < LL && col < DD) t = f32_to_tf32_rna(__ldg(&Wm[row * DD + col]));
        sW[i] = __uint_as_float(t);
    }
    for (int i = tid; i < VV * NN; i += NTHR1) sbins[i] = 0.f;
    for (int i = tid; i < VV; i += NTHR1) scnt[i] = 0;
    for (int i = tid; i < ntok; i += NTHR1) sids[i] = __ldg(&ids[b * SS + s0 + i]);
    __syncthreads();
    for (int i = tid; i < ntok; i += NTHR1) atomicAdd(&scnt[sids[i]], 1);

    // ---- Stage issue helper (6 cp.async 16B per thread per slice) ----
    const float* __restrict__ hb = h + (size_t)(b * SS + s0) * DD;
    const uint32_t aBase = smem_u32(smem + OFF_A);
    const int ctok = tid / 8;        // 64 tokens x 8 sub-threads... (3072/512=6 chunks)
    // chunk c in [0,3072): tok=c/48, off=c%48 ; thread handles c = tid + i*512

    #define STAGE(ST, BUF) do {                                                \
        const int _mt = (ST) >> 2, _ks = (ST) & 3;                             \
        _Pragma("unroll")                                                      \
        for (int _i = 0; _i < 6; ++_i) {                                       \
            const int _c   = tid + _i * NTHR1;                                 \
            const int _tok = _c / 48, _off = _c % 48;                          \
            const float* _src = hb + (size_t)(_mt * 64 + _tok) * DD            \
                                   + _ks * KS + _off * 4;                      \
            const uint32_t _dst = aBase + (BUF) * SZ_ABUF                      \
                                   + (_tok * APADF + _off * 4) * 4;            \
            asm volatile("cp.async.cg.shared.global [%0], [%1], 16;"           \
                         :: "r"(_dst), "l"(_src));                             \
        }                                                                      \
        asm volatile("cp.async.commit_group;");                                \
    } while (0)

    float acc[4] = {0.f, 0.f, 0.f, 0.f};

    STAGE(0, 0);

    for (int st = 0; st < nst; ++st) {
        const int ks = st & 3;
        if (ks == 0) { acc[0] = acc[1] = acc[2] = acc[3] = 0.f; }

        if (st + 1 < nst) {
            STAGE(st + 1, (st + 1) & 1);
            asm volatile("cp.async.wait_group 1;");
        } else {
            asm volatile("cp.async.wait_group 0;");
        }
        __syncthreads();

        // ---- Compute this slice: 24 k8 steps ----
        const float* A = (const float*)(smem + OFF_A + (st & 1) * SZ_ABUF);
        const float* aR0 = A + (mrow0 + g) * APADF + tig;
        const float* aR1 = A + (mrow0 + g + 8) * APADF + tig;
        const float* bR  = sW + (ncol0 + g) * WPADF + ks * KS + tig;
        #pragma unroll
        for (int step = 0; step < 24; ++step) {
            const int kb = step * 8;
            uint32_t a0 = __float_as_uint(aR0[kb]);
            uint32_t a1 = __float_as_uint(aR1[kb]);
            uint32_t a2 = __float_as_uint(aR0[kb + 4]);
            uint32_t a3 = __float_as_uint(aR1[kb + 4]);
            uint32_t b0 = __float_as_uint(bR[kb]);
            uint32_t b1 = __float_as_uint(bR[kb + 4]);
            mma_tf32(acc, a0, a1, a2, a3, b0, b1);
        }
        __syncthreads();

        // ---- Tile epilogue: bin logits by symbol ----
        if (ks == 3) {
            const int mt  = st >> 2;
            const int r0  = mrow0 + g;
            const int col = ncol0 + 2 * tig;
            const int id0 = sids[mt * 64 + r0];
            const int id1 = sids[mt * 64 + r0 + 8];
            atomicAdd(&sbins[id0 * NN + col],     acc[0]);
            atomicAdd(&sbins[id0 * NN + col + 1], acc[1]);
            atomicAdd(&sbins[id1 * NN + col],     acc[2]);
            atomicAdd(&sbins[id1 * NN + col + 1], acc[3]);
        }
    }
    __syncthreads();

    // ---- Flush bins + counts to scratch ----
    for (int i = tid; i < VV * NN; i += NTHR1)
        g_bins[cta * (VV * NN) + i] = sbins[i];
    for (int i = tid; i < VV; i += NTHR1)
        g_cnts[cta * VV + i] = scnt[i];
    (void)ctok;
}

// ---------------------------------------------------------------------------
// Kernel 2: thread per (segment, label) — reduce 18 chunks, mean+bias, mask.
__global__ __launch_bounds__(256) void k_head(
    const float* __restrict__ bias, float* __restrict__ out)
{
    const int idx = blockIdx.x * 256 + threadIdx.x;   // < 512*32
    const int seg = idx >> 5;
    const int l   = idx & 31;
    if (seg >= NSEG) return;
    const int b = seg >> 6, v = seg & 63;

    int c = 0;
    #pragma unroll
    for (int j = 0; j < NCH; ++j) c += g_cnts[(b * NCH + j) * VV + v];

    float s = 0.f;
    #pragma unroll
    for (int j = 0; j < NCH; ++j)
        s += g_bins[((b * NCH + j) * VV + v) * NN + l];

    if (l < LL) {
        float r = (v != 0 && c > 0)
                ? (s * COMP / (float)c + __ldg(&bias[l])) : 0.0f;
        out[seg * LL + l] = r;
    }
}

// ---------------------------------------------------------------------------
extern "C" void kernel_launch(void* const* d_in, const int* in_sizes, int n_in,
                              void* d_out, int out_size) {
    const float* h    = nullptr;   // 50331648
    const float* Wm   = nullptr;   // 19968
    const float* bias = nullptr;   // 26
    const int*   ids  = nullptr;   // 65536
    for (int i = 0; i < n_in; ++i) {
        switch (in_sizes[i]) {
            case BB * SS * DD: h    = (const float*)d_in[i]; break;
            case LL * DD:      Wm   = (const float*)d_in[i]; break;
            case LL:           bias = (const float*)d_in[i]; break;
            case BB * SS:      ids  = (const int*)d_in[i];   break;
        }
    }
    float* out = (float*)d_out;

    static bool attr_set = false;
    if (!attr_set) {
        cudaFuncSetAttribute(k_stream,
                             cudaFuncAttributeMaxDynamicSharedMemorySize, SMEMB);
        attr_set = true;
    }
    k_stream<<<NCTA, NTHR1, SMEMB>>>(h, ids, Wm);
    k_head<<<(NSEG * NN + 255) / 256, 256>>>(bias, out);
}